// round 12
// baseline (speedup 1.0000x reference)
#include <cuda_runtime.h>
#include <math.h>

#define B_ 16384
#define S_ 32
#define D_ 64
#define KTOP 3

constexpr int SD = S_ * D_;
constexpr long long OFF_READ_R = 0;
constexpr long long OFF_READ_I = (long long)B_ * D_;
constexpr long long OFF_NEXT_R = 2LL * B_ * D_;
constexpr long long OFF_NEXT_I = OFF_NEXT_R + (long long)B_ * SD;
constexpr long long OFF_ENT    = OFF_NEXT_I + (long long)B_ * SD;

__global__ void am_init_kernel(float* __restrict__ out) {
    out[OFF_ENT] = 0.0f;
}

__device__ __forceinline__ float dot4(float4 a, float4 b) {
    float s = a.x * b.x;
    s = fmaf(a.y, b.y, s);
    s = fmaf(a.z, b.z, s);
    s = fmaf(a.w, b.w, s);
    return s;
}

#define FULLM 0xffffffffu

// order-preserving float -> int key (involution)
__device__ __forceinline__ int f2key(float f) {
    int i = __float_as_int(f);
    return i ^ ((i >> 31) & 0x7fffffff);
}
__device__ __forceinline__ float key2f(int k) {
    return __int_as_float(k ^ ((k >> 31) & 0x7fffffff));
}
__device__ __forceinline__ float warp_fmax(float v) {
    return key2f(__reduce_max_sync(FULLM, f2key(v)));
}

__global__ __launch_bounds__(256, 6) void am_fused_kernel(
    const float* __restrict__ gw_r,  const float* __restrict__ gw_i,
    const float* __restrict__ mem_r, const float* __restrict__ mem_i,
    const float* __restrict__ Wg,    const float* __restrict__ bg,
    const float* __restrict__ Wa,    const float* __restrict__ ba,
    const float* __restrict__ gamma_r, const float* __restrict__ beta_r,
    const float* __restrict__ gamma_i, const float* __restrict__ beta_i,
    float* __restrict__ out)
{
    __shared__ float sim[S_], sparse[S_];
    __shared__ __align__(16) float wlog[8][S_];   // per-warp logit partials
    __shared__ __align__(16) float pr[8][D_];     // per-warp read_r partials
    __shared__ __align__(16) float pi_[8][D_];    // per-warp read_i partials
    __shared__ float s_wg;

    const int t    = threadIdx.x;
    const int b    = blockIdx.x;
    const int warp = t >> 5;
    const int lane = t & 31;
    const int sub  = t & 15;           // column group: cols 4*sub..4*sub+3
    const int rA   = t >> 4;           // row 0..15 ; rB = rA + 16
    const long long baseSD = (long long)b * SD;
    const long long baseD  = (long long)b * D_;

    // ---- contiguous vec4 loads: thread owns rows rA and rA+16, 4 cols each ----
    const float4* m4r = (const float4*)(mem_r + baseSD);
    const float4* m4i = (const float4*)(mem_i + baseSD);
    const float4 mrA = m4r[t];
    const float4 mrB = m4r[t + 256];
    const float4 miA = m4i[t];
    const float4 miB = m4i[t + 256];

    // ---- gw slices: direct LDG ----
    const float4 gwr4 = ((const float4*)(gw_r + baseD))[sub];
    const float4 gwi4 = ((const float4*)(gw_i + baseD))[sub];

    // ---- sim for rows rA, rA+16 : reduce-scatter over 16 lanes (4 shfls) ----
    {
        const float accA = dot4(mrA, gwr4) + dot4(miA, gwi4);
        const float accB = dot4(mrB, gwr4) + dot4(miB, gwi4);
        const bool hi = (lane & 8);
        const float recv = __shfl_xor_sync(FULLM, hi ? accA : accB, 8);
        float acc = (hi ? accB : accA) + recv;
        acc += __shfl_xor_sync(FULLM, acc, 4);
        acc += __shfl_xor_sync(FULLM, acc, 2);
        acc += __shfl_xor_sync(FULLM, acc, 1);
        if (sub == 0) sim[rA]      = acc;
        if (sub == 8) sim[rA + 16] = acc;
    }

    // ---- logits partials: warp w owns j in [16w,16w+16) ----
    {
        const int g = lane >> 3;
        const int k = lane & 7;
        const float* flatsrc = (warp < 4) ? (gw_r + baseD) : (gw_i + baseD);
        const int jb = (warp & 3) * 16;
        float4 lacc = make_float4(0.f, 0.f, 0.f, 0.f);
        #pragma unroll
        for (int i = 0; i < 4; i++) {
            const float f = flatsrc[jb + 4 * i + g];                 // LDG, L1 hit
            const float4 wa = ((const float4*)Wa)[(warp * 16 + 4 * i + g) * 8 + k];
            lacc.x = fmaf(f, wa.x, lacc.x);
            lacc.y = fmaf(f, wa.y, lacc.y);
            lacc.z = fmaf(f, wa.z, lacc.z);
            lacc.w = fmaf(f, wa.w, lacc.w);
        }
        lacc.x += __shfl_xor_sync(FULLM, lacc.x, 8);
        lacc.y += __shfl_xor_sync(FULLM, lacc.y, 8);
        lacc.z += __shfl_xor_sync(FULLM, lacc.z, 8);
        lacc.w += __shfl_xor_sync(FULLM, lacc.w, 8);
        lacc.x += __shfl_xor_sync(FULLM, lacc.x, 16);
        lacc.y += __shfl_xor_sync(FULLM, lacc.y, 16);
        lacc.z += __shfl_xor_sync(FULLM, lacc.z, 16);
        lacc.w += __shfl_xor_sync(FULLM, lacc.w, 16);
        if (lane < 8) ((float4*)&wlog[warp][0])[k] = lacc;
    }
    __syncthreads();   // B1: sim + wlog visible

    // ==== Phase B: every warp computes attn (cheap); warp1/2 do their scalar
    //      chains concurrently with the other warps' read-partials work. ====

    // ---- attention softmax, redundant per warp (lane l holds attn[l]) ----
    float attn_l;
    {
        const float v = sim[lane];
        const float m = warp_fmax(v);
        const float e = __expf(v - m);
        float ssum = e;
        #pragma unroll
        for (int o = 16; o; o >>= 1) ssum += __shfl_xor_sync(FULLM, ssum, o);
        attn_l = e / ssum;
    }

    // ---- read-vector partials (all warps) ----
    {
        const float aA = __shfl_sync(FULLM, attn_l, rA);
        const float aB = __shfl_sync(FULLM, attn_l, rA + 16);
        float vr[4] = { aA*mrA.x + aB*mrB.x, aA*mrA.y + aB*mrB.y,
                        aA*mrA.z + aB*mrB.z, aA*mrA.w + aB*mrB.w };
        float vi[4] = { aA*miA.x + aB*miB.x, aA*miA.y + aB*miB.y,
                        aA*miA.z + aB*miB.z, aA*miA.w + aB*miB.w };
        #pragma unroll
        for (int i = 0; i < 4; i++) {
            vr[i] += __shfl_xor_sync(FULLM, vr[i], 16);
            vi[i] += __shfl_xor_sync(FULLM, vi[i], 16);
        }
        if (lane < 16) {
            ((float4*)&pr[warp][0])[lane]  = make_float4(vr[0], vr[1], vr[2], vr[3]);
            ((float4*)&pi_[warp][0])[lane] = make_float4(vi[0], vi[1], vi[2], vi[3]);
        }
    }

    if (warp == 1) {
        // ---- write softmax + fused entropy + top-3 sparse ----
        float v = ba[lane];
        #pragma unroll
        for (int w = 0; w < 8; w++) v += wlog[w][lane];
        const float m = warp_fmax(v);
        const float d = v - m;
        const float e = __expf(d);
        float ssum = e;
        float dsum = e * d;
        #pragma unroll
        for (int o = 16; o; o >>= 1) {          // paired tree, ILP-overlapped
            ssum += __shfl_xor_sync(FULLM, ssum, o);
            dsum += __shfl_xor_sync(FULLM, dsum, o);
        }
        const float w_ = e / ssum;
        if (lane == 0) {
            // H = -sum w log w = log(ssum) - dsum/ssum
            const float H = __logf(ssum) - dsum / ssum;
            atomicAdd(out + OFF_ENT, H * (1.0f / (float)B_));
        }

        // top-3 via redux-max + ballot (positive probs: int order == float order)
        float vv = w_;
        float sp = 0.0f;
        float sumTop = 0.0f;
        #pragma unroll
        for (int k = 0; k < KTOP; k++) {
            const int mkey = __reduce_max_sync(FULLM, __float_as_int(vv));
            const float mv = __int_as_float(mkey);
            const unsigned msk = __ballot_sync(FULLM, vv == mv);
            const int mi = __ffs(msk) - 1;      // tie -> lowest index
            sumTop += mv;
            if (lane == mi) { sp = mv; vv = -INFINITY; }
        }
        sparse[lane] = sp / (sumTop + 1e-6f);
    } else if (warp == 2) {
        // ---- write gate ----
        float acc = 0.0f;
        #pragma unroll
        for (int i = 0; i < 4; i++) {
            const int j = lane + i * 32;
            const float f = (j < 64) ? gw_r[baseD + j] : gw_i[baseD + j - 64];
            acc = fmaf(f, Wg[j], acc);
        }
        #pragma unroll
        for (int o = 16; o; o >>= 1) acc += __shfl_xor_sync(FULLM, acc, o);
        if (lane == 0) s_wg = 1.0f / (1.0f + __expf(-(acc + bg[0])));
    }
    __syncthreads();   // B2: sparse, s_wg, pr, pi_ visible

    // ---- memory update + LayerNorm (parts: 0=realA, 1=realB, 2=imagA, 3=imagB) ----
    {
        const float sw   = s_wg;
        const float effA = sw * sparse[rA];
        const float effB = sw * sparse[rA + 16];
        const float omA  = 1.0f - effA;
        const float omB  = 1.0f - effB;

        // pass 1: per-part partial sum / sumsq over this thread's 4 elements
        float s_[4], q_[4];
        #pragma unroll
        for (int part = 0; part < 4; part++) {
            const float4 src = (part == 0) ? mrA : (part == 1) ? mrB
                             : (part == 2) ? miA : miB;
            const float4 g   = (part < 2) ? gwr4 : gwi4;
            const float  eff = (part & 1) ? effB : effA;
            const float  om  = (part & 1) ? omB  : omA;
            const float v0 = om * src.x + eff * g.x;
            const float v1 = om * src.y + eff * g.y;
            const float v2 = om * src.z + eff * g.z;
            const float v3 = om * src.w + eff * g.w;
            s_[part] = v0 + v1 + v2 + v3;
            q_[part] = fmaf(v0, v0, fmaf(v1, v1, fmaf(v2, v2, v3 * v3)));
        }

        // reduce-scatter over 16-lane group: o=8 splits real|imag, o=4 splits A|B
        const bool hi8 = (lane & 8);
        const float r0 = __shfl_xor_sync(FULLM, hi8 ? s_[0] : s_[2], 8);
        const float r1 = __shfl_xor_sync(FULLM, hi8 ? q_[0] : q_[2], 8);
        const float r2 = __shfl_xor_sync(FULLM, hi8 ? s_[1] : s_[3], 8);
        const float r3 = __shfl_xor_sync(FULLM, hi8 ? q_[1] : q_[3], 8);
        const float sa = (hi8 ? s_[2] : s_[0]) + r0;
        const float qa = (hi8 ? q_[2] : q_[0]) + r1;
        const float sb = (hi8 ? s_[3] : s_[1]) + r2;
        const float qb = (hi8 ? q_[3] : q_[1]) + r3;

        const bool hi4 = (lane & 4);
        const float rs = __shfl_xor_sync(FULLM, hi4 ? sa : sb, 4);
        const float rq = __shfl_xor_sync(FULLM, hi4 ? qa : qb, 4);
        float ss = (hi4 ? sb : sa) + rs;
        float qq = (hi4 ? qb : qa) + rq;

        ss += __shfl_xor_sync(FULLM, ss, 2);
        qq += __shfl_xor_sync(FULLM, qq, 2);
        ss += __shfl_xor_sync(FULLM, ss, 1);
        qq += __shfl_xor_sync(FULLM, qq, 1);

        const float mean_m = ss * (1.0f / 64.0f);
        const float var_m  = qq * (1.0f / 64.0f) - mean_m * mean_m;
        const float rstd_m = rsqrtf(var_m + 1e-5f);

        // broadcast each part's (mean, rstd) from its owning quad
        float mean[4], rstd[4];
        #pragma unroll
        for (int p = 0; p < 4; p++) {
            const int src = (lane & 16) | (p << 2) | (lane & 3);
            mean[p] = __shfl_sync(FULLM, mean_m, src);
            rstd[p] = __shfl_sync(FULLM, rstd_m, src);
        }

        const float4 gr4 = ((const float4*)gamma_r)[sub];
        const float4 br4 = ((const float4*)beta_r)[sub];
        const float4 gi4 = ((const float4*)gamma_i)[sub];
        const float4 bi4 = ((const float4*)beta_i)[sub];

        float4* outR = (float4*)(out + OFF_NEXT_R + baseSD);
        float4* outI = (float4*)(out + OFF_NEXT_I + baseSD);

        // pass 2: recompute v, normalize, store
        #pragma unroll
        for (int part = 0; part < 4; part++) {
            const float4 src = (part == 0) ? mrA : (part == 1) ? mrB
                             : (part == 2) ? miA : miB;
            const float4 g   = (part < 2) ? gwr4 : gwi4;
            const float  eff = (part & 1) ? effB : effA;
            const float  om  = (part & 1) ? omB  : omA;
            const float  mn  = mean[part];
            const float  rs2 = rstd[part];

            const float v0 = om * src.x + eff * g.x;
            const float v1 = om * src.y + eff * g.y;
            const float v2 = om * src.z + eff * g.z;
            const float v3 = om * src.w + eff * g.w;

            const float4 gam = (part < 2) ? gr4 : gi4;
            const float4 bet = (part < 2) ? br4 : bi4;
            float4 o4;
            o4.x = fmaf((v0 - mn) * rs2, gam.x, bet.x);
            o4.y = fmaf((v1 - mn) * rs2, gam.y, bet.y);
            o4.z = fmaf((v2 - mn) * rs2, gam.z, bet.z);
            o4.w = fmaf((v3 - mn) * rs2, gam.w, bet.w);

            float4* dst = (part < 2) ? outR : outI;
            dst[(part & 1) ? (t + 256) : t] = o4;
        }
    }

    // ---- read-vector reduction (pr/pi_ complete since B2; no extra barrier) ----
    if (t < 128) {
        const int d = t & 63;
        const float* src = (t < 64) ? &pr[0][0] : &pi_[0][0];
        float s = 0.0f;
        #pragma unroll
        for (int w = 0; w < 8; w++) s += src[w * D_ + d];
        const long long off = ((t < 64) ? OFF_READ_R : OFF_READ_I) + (long long)b * D_ + d;
        out[off] = s;
    }
}

extern "C" void kernel_launch(void* const* d_in, const int* in_sizes, int n_in,
                              void* d_out, int out_size)
{
    const float* gw_r    = (const float*)d_in[0];
    const float* gw_i    = (const float*)d_in[1];
    const float* mem_r   = (const float*)d_in[2];
    const float* mem_i   = (const float*)d_in[3];
    const float* Wg      = (const float*)d_in[4];
    const float* bg      = (const float*)d_in[5];
    const float* Wa      = (const float*)d_in[6];
    const float* ba      = (const float*)d_in[7];
    const float* gamma_r = (const float*)d_in[8];
    const float* beta_r  = (const float*)d_in[9];
    const float* gamma_i = (const float*)d_in[10];
    const float* beta_i  = (const float*)d_in[11];
    float* out = (float*)d_out;

    am_init_kernel<<<1, 1>>>(out);
    am_fused_kernel<<<B_, 256>>>(gw_r, gw_i, mem_r, mem_i, Wg, bg, Wa, ba,
                                 gamma_r, beta_r, gamma_i, beta_i, out);
}

// round 13
// speedup vs baseline: 1.0364x; 1.0364x over previous
#include <cuda_runtime.h>
#include <math.h>

#define B_ 16384
#define S_ 32
#define D_ 64
#define KTOP 3

constexpr int SD = S_ * D_;
constexpr long long OFF_READ_R = 0;
constexpr long long OFF_READ_I = (long long)B_ * D_;
constexpr long long OFF_NEXT_R = 2LL * B_ * D_;
constexpr long long OFF_NEXT_I = OFF_NEXT_R + (long long)B_ * SD;
constexpr long long OFF_ENT    = OFF_NEXT_I + (long long)B_ * SD;

__global__ void am_init_kernel(float* __restrict__ out) {
    out[OFF_ENT] = 0.0f;
}

__device__ __forceinline__ float dot4(float4 a, float4 b) {
    float s = a.x * b.x;
    s = fmaf(a.y, b.y, s);
    s = fmaf(a.z, b.z, s);
    s = fmaf(a.w, b.w, s);
    return s;
}

#define FULLM 0xffffffffu

// order-preserving float -> int key (involution)
__device__ __forceinline__ int f2key(float f) {
    int i = __float_as_int(f);
    return i ^ ((i >> 31) & 0x7fffffff);
}
__device__ __forceinline__ float key2f(int k) {
    return __int_as_float(k ^ ((k >> 31) & 0x7fffffff));
}
__device__ __forceinline__ float warp_fmax(float v) {
    return key2f(__reduce_max_sync(FULLM, f2key(v)));
}

__global__ __launch_bounds__(256, 6) void am_fused_kernel(
    const float* __restrict__ gw_r,  const float* __restrict__ gw_i,
    const float* __restrict__ mem_r, const float* __restrict__ mem_i,
    const float* __restrict__ Wg,    const float* __restrict__ bg,
    const float* __restrict__ Wa,    const float* __restrict__ ba,
    const float* __restrict__ gamma_r, const float* __restrict__ beta_r,
    const float* __restrict__ gamma_i, const float* __restrict__ beta_i,
    float* __restrict__ out)
{
    __shared__ float sim[S_], attn[S_], sparse[S_];
    __shared__ __align__(16) float wlog[8][S_];   // per-warp logit partials
    __shared__ __align__(16) float pr[8][D_];     // per-warp read_r partials
    __shared__ __align__(16) float pi_[8][D_];    // per-warp read_i partials
    __shared__ float s_wg;

    const int t    = threadIdx.x;
    const int b    = blockIdx.x;
    const int warp = t >> 5;
    const int lane = t & 31;
    const int sub  = t & 15;           // column group: cols 4*sub..4*sub+3
    const int rA   = t >> 4;           // row 0..15 ; rB = rA + 16
    const long long baseSD = (long long)b * SD;
    const long long baseD  = (long long)b * D_;

    // ---- contiguous vec4 loads: thread owns rows rA and rA+16, 4 cols each ----
    const float4* m4r = (const float4*)(mem_r + baseSD);
    const float4* m4i = (const float4*)(mem_i + baseSD);
    const float4 mrA = m4r[t];
    const float4 mrB = m4r[t + 256];
    const float4 miA = m4i[t];
    const float4 miB = m4i[t + 256];

    // ---- gw slices: direct LDG ----
    const float4 gwr4 = ((const float4*)(gw_r + baseD))[sub];
    const float4 gwi4 = ((const float4*)(gw_i + baseD))[sub];

    // ---- sim for rows rA, rA+16 : reduce-scatter over 16 lanes (4 shfls) ----
    {
        const float accA = dot4(mrA, gwr4) + dot4(miA, gwi4);
        const float accB = dot4(mrB, gwr4) + dot4(miB, gwi4);
        const bool hi = (lane & 8);
        const float recv = __shfl_xor_sync(FULLM, hi ? accA : accB, 8);
        float acc = (hi ? accB : accA) + recv;
        acc += __shfl_xor_sync(FULLM, acc, 4);
        acc += __shfl_xor_sync(FULLM, acc, 2);
        acc += __shfl_xor_sync(FULLM, acc, 1);
        if (sub == 0) sim[rA]      = acc;
        if (sub == 8) sim[rA + 16] = acc;
    }

    // ---- logits partials: warp w owns j in [16w,16w+16) ----
    // lane = 8*g + k : g=row-within-quad (0..3), k=s-quad (0..7)
    // reduce-scatter over the 4 g-groups in 3 shfls; lane ends owning
    // logit s = 4k + g, stored as one conflict-free scalar STS.
    {
        const int g = lane >> 3;
        const int k = lane & 7;
        const float* flatsrc = (warp < 4) ? (gw_r + baseD) : (gw_i + baseD);
        const int jb = (warp & 3) * 16;
        float4 lacc = make_float4(0.f, 0.f, 0.f, 0.f);
        #pragma unroll
        for (int i = 0; i < 4; i++) {
            const float f = flatsrc[jb + 4 * i + g];                 // LDG, L1 hit
            const float4 wa = ((const float4*)Wa)[(warp * 16 + 4 * i + g) * 8 + k];
            lacc.x = fmaf(f, wa.x, lacc.x);
            lacc.y = fmaf(f, wa.y, lacc.y);
            lacc.z = fmaf(f, wa.z, lacc.z);
            lacc.w = fmaf(f, wa.w, lacc.w);
        }
        const bool g1 = (g & 2);
        // step 1 (offset 16): exchange the component pair the partner keeps
        const float sA = __shfl_xor_sync(FULLM, g1 ? lacc.x : lacc.z, 16);
        const float sB = __shfl_xor_sync(FULLM, g1 ? lacc.y : lacc.w, 16);
        const float keep0 = (g1 ? lacc.z : lacc.x) + sA;   // comp c = g1?2:0
        const float keep1 = (g1 ? lacc.w : lacc.y) + sB;   // comp c = g1?3:1
        // step 2 (offset 8): exchange the single component the partner keeps
        const bool g0 = (g & 1);
        const float sC = __shfl_xor_sync(FULLM, g0 ? keep0 : keep1, 8);
        const float fin = (g0 ? keep1 : keep0) + sC;       // full sum, comp c = g
        wlog[warp][4 * k + g] = fin;
    }
    __syncthreads();   // B1: sim + wlog visible

    if (warp == 0) {
        // ---- attention softmax over S=32 (redux max, shfl sum) ----
        const float v = sim[lane];
        const float m = warp_fmax(v);
        const float e = __expf(v - m);
        float ssum = e;
        #pragma unroll
        for (int o = 16; o; o >>= 1) ssum += __shfl_xor_sync(FULLM, ssum, o);
        attn[lane] = e / ssum;
    } else if (warp == 1) {
        // ---- write softmax + fused entropy + top-3 sparse ----
        float v = ba[lane];
        #pragma unroll
        for (int w = 0; w < 8; w++) v += wlog[w][lane];
        const float m = warp_fmax(v);
        const float d = v - m;
        const float e = __expf(d);
        float ssum = e;
        float dsum = e * d;
        #pragma unroll
        for (int o = 16; o; o >>= 1) {          // paired tree, ILP-overlapped
            ssum += __shfl_xor_sync(FULLM, ssum, o);
            dsum += __shfl_xor_sync(FULLM, dsum, o);
        }
        const float w_ = e / ssum;
        if (lane == 0) {
            // H = -sum w log w = log(ssum) - dsum/ssum
            const float H = __logf(ssum) - dsum / ssum;
            atomicAdd(out + OFF_ENT, H * (1.0f / (float)B_));
        }

        // top-3 via redux-max + ballot (positive probs: int order == float order)
        float vv = w_;
        float sp = 0.0f;
        float sumTop = 0.0f;
        #pragma unroll
        for (int k = 0; k < KTOP; k++) {
            const int mkey = __reduce_max_sync(FULLM, __float_as_int(vv));
            const float mv = __int_as_float(mkey);
            const unsigned msk = __ballot_sync(FULLM, vv == mv);
            const int mi = __ffs(msk) - 1;      // tie -> lowest index
            sumTop += mv;
            if (lane == mi) { sp = mv; vv = -INFINITY; }
        }
        sparse[lane] = sp / (sumTop + 1e-6f);
    } else if (warp == 2) {
        // ---- write gate ----
        float acc = 0.0f;
        #pragma unroll
        for (int i = 0; i < 4; i++) {
            const int j = lane + i * 32;
            const float f = (j < 64) ? gw_r[baseD + j] : gw_i[baseD + j - 64];
            acc = fmaf(f, Wg[j], acc);
        }
        #pragma unroll
        for (int o = 16; o; o >>= 1) acc += __shfl_xor_sync(FULLM, acc, o);
        if (lane == 0) s_wg = 1.0f / (1.0f + __expf(-(acc + bg[0])));
    }
    __syncthreads();   // B2: attn, sparse, s_wg visible

    // ---- read-vector partials: reduce-scatter the offset-16 fold (4 shfls) ----
    {
        const float aA = attn[rA];
        const float aB = attn[rA + 16];
        float vr[4] = { aA*mrA.x + aB*mrB.x, aA*mrA.y + aB*mrB.y,
                        aA*mrA.z + aB*mrB.z, aA*mrA.w + aB*mrB.w };
        float vi[4] = { aA*miA.x + aB*miB.x, aA*miA.y + aB*miB.y,
                        aA*miA.z + aB*miB.z, aA*miA.w + aB*miB.w };
        const bool hiL = (lane & 16);
        float res[4];
        #pragma unroll
        for (int i = 0; i < 4; i++) {
            const float recv = __shfl_xor_sync(FULLM, hiL ? vr[i] : vi[i], 16);
            res[i] = (hiL ? vi[i] : vr[i]) + recv;   // low: vr total, high: vi total
        }
        if (!hiL) ((float4*)&pr[warp][0])[sub]  = make_float4(res[0], res[1], res[2], res[3]);
        else      ((float4*)&pi_[warp][0])[sub] = make_float4(res[0], res[1], res[2], res[3]);
    }

    // ---- memory update + LayerNorm (parts: 0=realA, 1=realB, 2=imagA, 3=imagB) ----
    {
        const float sw   = s_wg;
        const float effA = sw * sparse[rA];
        const float effB = sw * sparse[rA + 16];
        const float omA  = 1.0f - effA;
        const float omB  = 1.0f - effB;

        // pass 1: per-part partial sum / sumsq over this thread's 4 elements
        float s_[4], q_[4];
        #pragma unroll
        for (int part = 0; part < 4; part++) {
            const float4 src = (part == 0) ? mrA : (part == 1) ? mrB
                             : (part == 2) ? miA : miB;
            const float4 g   = (part < 2) ? gwr4 : gwi4;
            const float  eff = (part & 1) ? effB : effA;
            const float  om  = (part & 1) ? omB  : omA;
            const float v0 = om * src.x + eff * g.x;
            const float v1 = om * src.y + eff * g.y;
            const float v2 = om * src.z + eff * g.z;
            const float v3 = om * src.w + eff * g.w;
            s_[part] = v0 + v1 + v2 + v3;
            q_[part] = fmaf(v0, v0, fmaf(v1, v1, fmaf(v2, v2, v3 * v3)));
        }

        // reduce-scatter over 16-lane group: o=8 splits real|imag, o=4 splits A|B
        const bool hi8 = (lane & 8);
        const float r0 = __shfl_xor_sync(FULLM, hi8 ? s_[0] : s_[2], 8);
        const float r1 = __shfl_xor_sync(FULLM, hi8 ? q_[0] : q_[2], 8);
        const float r2 = __shfl_xor_sync(FULLM, hi8 ? s_[1] : s_[3], 8);
        const float r3 = __shfl_xor_sync(FULLM, hi8 ? q_[1] : q_[3], 8);
        const float sa = (hi8 ? s_[2] : s_[0]) + r0;
        const float qa = (hi8 ? q_[2] : q_[0]) + r1;
        const float sb = (hi8 ? s_[3] : s_[1]) + r2;
        const float qb = (hi8 ? q_[3] : q_[1]) + r3;

        const bool hi4 = (lane & 4);
        const float rs = __shfl_xor_sync(FULLM, hi4 ? sa : sb, 4);
        const float rq = __shfl_xor_sync(FULLM, hi4 ? qa : qb, 4);
        float ss = (hi4 ? sb : sa) + rs;
        float qq = (hi4 ? qb : qa) + rq;

        ss += __shfl_xor_sync(FULLM, ss, 2);
        qq += __shfl_xor_sync(FULLM, qq, 2);
        ss += __shfl_xor_sync(FULLM, ss, 1);
        qq += __shfl_xor_sync(FULLM, qq, 1);

        const float mean_m = ss * (1.0f / 64.0f);
        const float var_m  = qq * (1.0f / 64.0f) - mean_m * mean_m;
        const float rstd_m = rsqrtf(var_m + 1e-5f);

        // broadcast each part's (mean, rstd) from its owning quad
        float mean[4], rstd[4];
        #pragma unroll
        for (int p = 0; p < 4; p++) {
            const int src = (lane & 16) | (p << 2) | (lane & 3);
            mean[p] = __shfl_sync(FULLM, mean_m, src);
            rstd[p] = __shfl_sync(FULLM, rstd_m, src);
        }

        const float4 gr4 = ((const float4*)gamma_r)[sub];
        const float4 br4 = ((const float4*)beta_r)[sub];
        const float4 gi4 = ((const float4*)gamma_i)[sub];
        const float4 bi4 = ((const float4*)beta_i)[sub];

        float4* outR = (float4*)(out + OFF_NEXT_R + baseSD);
        float4* outI = (float4*)(out + OFF_NEXT_I + baseSD);

        // pass 2: recompute v, normalize, store
        #pragma unroll
        for (int part = 0; part < 4; part++) {
            const float4 src = (part == 0) ? mrA : (part == 1) ? mrB
                             : (part == 2) ? miA : miB;
            const float4 g   = (part < 2) ? gwr4 : gwi4;
            const float  eff = (part & 1) ? effB : effA;
            const float  om  = (part & 1) ? omB  : omA;
            const float  mn  = mean[part];
            const float  rs2 = rstd[part];

            const float v0 = om * src.x + eff * g.x;
            const float v1 = om * src.y + eff * g.y;
            const float v2 = om * src.z + eff * g.z;
            const float v3 = om * src.w + eff * g.w;

            const float4 gam = (part < 2) ? gr4 : gi4;
            const float4 bet = (part < 2) ? br4 : bi4;
            float4 o4;
            o4.x = fmaf((v0 - mn) * rs2, gam.x, bet.x);
            o4.y = fmaf((v1 - mn) * rs2, gam.y, bet.y);
            o4.z = fmaf((v2 - mn) * rs2, gam.z, bet.z);
            o4.w = fmaf((v3 - mn) * rs2, gam.w, bet.w);

            float4* dst = (part < 2) ? outR : outI;
            dst[(part & 1) ? (t + 256) : t] = o4;
        }
    }

    // ---- final read-vector reduction ----
    __syncthreads();   // B3: pr/pi_ complete
    if (t < 128) {
        const int d = t & 63;
        const float* src = (t < 64) ? &pr[0][0] : &pi_[0][0];
        float s = 0.0f;
        #pragma unroll
        for (int w = 0; w < 8; w++) s += src[w * D_ + d];
        const long long off = ((t < 64) ? OFF_READ_R : OFF_READ_I) + (long long)b * D_ + d;
        out[off] = s;
    }
}

extern "C" void kernel_launch(void* const* d_in, const int* in_sizes, int n_in,
                              void* d_out, int out_size)
{
    const float* gw_r    = (const float*)d_in[0];
    const float* gw_i    = (const float*)d_in[1];
    const float* mem_r   = (const float*)d_in[2];
    const float* mem_i   = (const float*)d_in[3];
    const float* Wg      = (const float*)d_in[4];
    const float* bg      = (const float*)d_in[5];
    const float* Wa      = (const float*)d_in[6];
    const float* ba      = (const float*)d_in[7];
    const float* gamma_r = (const float*)d_in[8];
    const float* beta_r  = (const float*)d_in[9];
    const float* gamma_i = (const float*)d_in[10];
    const float* beta_i  = (const float*)d_in[11];
    float* out = (float*)d_out;

    am_init_kernel<<<1, 1>>>(out);
    am_fused_kernel<<<B_, 256>>>(gw_r, gw_i, mem_r, mem_i, Wg, bg, Wa, ba,
                                 gamma_r, beta_r, gamma_i, beta_i, out);
}